// round 1
// baseline (speedup 1.0000x reference)
#include <cuda_runtime.h>
#include <cstdint>

// Problem constants
#define E_TOT   32768
#define N_NODES 2048
#define D       128      // all hidden dims
#define DF      32       // feature dim
#define DCAT    160      // D + DF
#define MAXED   64       // per-edge node-degree cap (mean ~10.2, binomial tail << 64)

// smem strides (floats). XS=65: conflict-free scalar a-loads + conflict-free STS fill.
// WS=132: float4-aligned, conflict-free float4 w-loads along contiguous 512B rows.
#define XS 65
#define WS 132

// Scratch (allocation-free rule: __device__ globals)
__device__ float g_h1[(size_t)E_TOT * D];
__device__ float g_s [(size_t)E_TOT * D];
__device__ float g_node[(size_t)N_NODES * D];
__device__ int   g_edeg[E_TOT];
__device__ int   g_enode[(size_t)E_TOT * MAXED];

__device__ __forceinline__ float lsig(float x) {
    // log_sigmoid(x) = min(x,0) - log1p(exp(-|x|))
    return fminf(x, 0.0f) - log1pf(__expf(-fabsf(x)));
}

__global__ void zero_kernel() {
    int i = blockIdx.x * blockDim.x + threadIdx.x;
    if (i < E_TOT) g_edeg[i] = 0;
}

// ---------------------------------------------------------------------------
// Generic fused GEMM + log_sigmoid: out[E,128] = ls(in[E,128] @ W[128,128]^T (+b))
// Block: 64 rows x 128 cols, 256 threads, 4x8 micro-tile.
// ---------------------------------------------------------------------------
template<bool HASB>
__global__ void __launch_bounds__(256) mlp_kernel(const float* __restrict__ in,
                                                  const float* __restrict__ W,
                                                  const float* __restrict__ b,
                                                  float* __restrict__ out) {
    extern __shared__ float sm[];
    float* xT = sm;              // [128][XS]  (k-major input tile)
    float* wT = xT + 128 * XS;   // [128][WS]  (k-major weights)
    float* sb = wT + 128 * WS;   // [128] bias

    const int tid = threadIdx.x;
    const int e0  = blockIdx.x * 64;

    // Stage input tile (coalesced global read, k-major STS)
    const float* inb = in + (size_t)e0 * 128;
    for (int idx = tid; idx < 64 * 128; idx += 256) {
        int m = idx >> 7, k = idx & 127;
        xT[k * XS + m] = inb[idx];
    }
    // Stage weights transposed: wT[k][n] = W[n][k]
    for (int idx = tid; idx < 128 * 128; idx += 256) {
        int n = idx >> 7, k = idx & 127;
        wT[k * WS + n] = W[idx];
    }
    if (HASB && tid < 128) sb[tid] = b[tid];
    __syncthreads();

    const int tr = tid >> 4;   // 0..15 row group
    const int tc = tid & 15;   // 0..15 col group
    float acc[4][8];
#pragma unroll
    for (int i = 0; i < 4; ++i)
#pragma unroll
        for (int j = 0; j < 8; ++j) acc[i][j] = 0.0f;

#pragma unroll 8
    for (int k = 0; k < 128; ++k) {
        const float* xk = xT + k * XS + tr * 4;
        float av[4] = {xk[0], xk[1], xk[2], xk[3]};
        const float4* wk = reinterpret_cast<const float4*>(wT + k * WS) + tc * 2;
        float4 w0 = wk[0], w1 = wk[1];
        float wv[8] = {w0.x, w0.y, w0.z, w0.w, w1.x, w1.y, w1.z, w1.w};
#pragma unroll
        for (int i = 0; i < 4; ++i)
#pragma unroll
            for (int j = 0; j < 8; ++j)
                acc[i][j] += av[i] * wv[j];
    }

#pragma unroll
    for (int i = 0; i < 4; ++i) {
        int row = e0 + tr * 4 + i;
        float r[8];
#pragma unroll
        for (int j = 0; j < 8; ++j) {
            float v = acc[i][j];
            if (HASB) v += sb[tc * 8 + j];
            r[j] = lsig(v);
        }
        float4* op = reinterpret_cast<float4*>(out + (size_t)row * 128 + tc * 8);
        op[0] = make_float4(r[0], r[1], r[2], r[3]);
        op[1] = make_float4(r[4], r[5], r[6], r[7]);
    }
}

// ---------------------------------------------------------------------------
// Mask scan (DRAM-bound, 268MB): one block per node row.
//  - accumulates node_sum[n][:] = sum over incident edges of s[e][:]  (L2 reads)
//  - appends (e -> n) into edge-major adjacency lists (for the reverse pass)
// ---------------------------------------------------------------------------
__global__ void __launch_bounds__(128) scan_kernel(const float* __restrict__ mask) {
    const int n = blockIdx.x;
    const int t = threadIdx.x;
    __shared__ int s_cnt;
    __shared__ int s_list[512];

    const float4* mrow = reinterpret_cast<const float4*>(mask + (size_t)n * E_TOT);
    float acc = 0.0f;

    for (int base = 0; base < E_TOT; base += 512) {
        if (t == 0) s_cnt = 0;
        __syncthreads();
        float4 mv = mrow[(base >> 2) + t];
        int e0 = base + t * 4;
        if (mv.x != 0.0f) s_list[atomicAdd(&s_cnt, 1)] = e0;
        if (mv.y != 0.0f) s_list[atomicAdd(&s_cnt, 1)] = e0 + 1;
        if (mv.z != 0.0f) s_list[atomicAdd(&s_cnt, 1)] = e0 + 2;
        if (mv.w != 0.0f) s_list[atomicAdd(&s_cnt, 1)] = e0 + 3;
        __syncthreads();
        int c = s_cnt;
        for (int i = 0; i < c; ++i) {
            int e = s_list[i];
            acc += g_s[(size_t)e * 128 + t];        // coalesced 512B row read
        }
        for (int i = t; i < c; i += 128) {
            int e = s_list[i];
            int p = atomicAdd(&g_edeg[e], 1);
            if (p < MAXED) g_enode[(size_t)e * MAXED + p] = n;
        }
        __syncthreads();
    }
    g_node[(size_t)n * 128 + t] = acc;
}

// ---------------------------------------------------------------------------
// Fused final stage: build cat = [maskT@node - s, feature] on the fly, then
// out = ls( ls(cat @ W1a^T + b1a) @ W2a^T ).  One kernel, agg never hits DRAM.
// ---------------------------------------------------------------------------
__global__ void __launch_bounds__(256) final_kernel(const float* __restrict__ feature,
                                                    const float* __restrict__ W1a,
                                                    const float* __restrict__ b1a,
                                                    const float* __restrict__ W2a,
                                                    float* __restrict__ out) {
    extern __shared__ float sm[];
    float* xT = sm;                   // [160][XS]  cat tile, k-major
    float* wT = xT + DCAT * XS;       // [160][WS]  W1a then W2a (reused)
    float* hT = wT + DCAT * WS;       // [128][XS]  hidden tile, k-major
    float* sb = hT + 128 * XS;        // [128]

    const int tid = threadIdx.x;
    const int e0  = blockIdx.x * 64;

    // Build agg part of xT: 4 threads per edge, each owns a 32-dim slab
    {
        int m  = tid >> 2;
        int kb = (tid & 3) << 5;
        int e  = e0 + m;
        float v[32];
        const float4* sp = reinterpret_cast<const float4*>(g_s + (size_t)e * 128 + kb);
#pragma unroll
        for (int q = 0; q < 8; ++q) {
            float4 f = sp[q];
            v[q * 4 + 0] = -f.x; v[q * 4 + 1] = -f.y;
            v[q * 4 + 2] = -f.z; v[q * 4 + 3] = -f.w;
        }
        int d = g_edeg[e];
        if (d > MAXED) d = MAXED;
        for (int i = 0; i < d; ++i) {
            int nn = g_enode[(size_t)e * MAXED + i];
            const float4* np = reinterpret_cast<const float4*>(g_node + (size_t)nn * 128 + kb);
#pragma unroll
            for (int q = 0; q < 8; ++q) {
                float4 f = np[q];
                v[q * 4 + 0] += f.x; v[q * 4 + 1] += f.y;
                v[q * 4 + 2] += f.z; v[q * 4 + 3] += f.w;
            }
        }
#pragma unroll
        for (int kk = 0; kk < 32; ++kk) xT[(kb + kk) * XS + m] = v[kk];
    }
    // Feature part of xT (k = 128..159)
    for (int idx = tid; idx < 64 * DF; idx += 256) {
        int m = idx >> 5, k = idx & 31;
        xT[(128 + k) * XS + m] = feature[(size_t)(e0 + m) * DF + k];
    }
    // Stage W1a transposed
    for (int idx = tid; idx < 128 * DCAT; idx += 256) {
        int n = idx / DCAT, k = idx - n * DCAT;
        wT[k * WS + n] = W1a[idx];
    }
    if (tid < 128) sb[tid] = b1a[tid];
    __syncthreads();

    const int tr = tid >> 4, tc = tid & 15;
    float acc[4][8];
#pragma unroll
    for (int i = 0; i < 4; ++i)
#pragma unroll
        for (int j = 0; j < 8; ++j) acc[i][j] = 0.0f;

    // GEMM1: K = 160
#pragma unroll 8
    for (int k = 0; k < DCAT; ++k) {
        const float* xk = xT + k * XS + tr * 4;
        float av[4] = {xk[0], xk[1], xk[2], xk[3]};
        const float4* wk = reinterpret_cast<const float4*>(wT + k * WS) + tc * 2;
        float4 w0 = wk[0], w1 = wk[1];
        float wv[8] = {w0.x, w0.y, w0.z, w0.w, w1.x, w1.y, w1.z, w1.w};
#pragma unroll
        for (int i = 0; i < 4; ++i)
#pragma unroll
            for (int j = 0; j < 8; ++j)
                acc[i][j] += av[i] * wv[j];
    }
    // h = ls(acc + b) -> hT (k-major)
#pragma unroll
    for (int i = 0; i < 4; ++i)
#pragma unroll
        for (int j = 0; j < 8; ++j) {
            int col = tc * 8 + j;
            hT[col * XS + tr * 4 + i] = lsig(acc[i][j] + sb[col]);
        }
    __syncthreads();   // all GEMM1 wT reads done; hT complete

    // Stage W2a transposed (overwrites W1a region)
    for (int idx = tid; idx < 128 * 128; idx += 256) {
        int n = idx >> 7, k = idx & 127;
        wT[k * WS + n] = W2a[idx];
    }
    __syncthreads();

#pragma unroll
    for (int i = 0; i < 4; ++i)
#pragma unroll
        for (int j = 0; j < 8; ++j) acc[i][j] = 0.0f;

    // GEMM2: K = 128
#pragma unroll 8
    for (int k = 0; k < 128; ++k) {
        const float* xk = hT + k * XS + tr * 4;
        float av[4] = {xk[0], xk[1], xk[2], xk[3]};
        const float4* wk = reinterpret_cast<const float4*>(wT + k * WS) + tc * 2;
        float4 w0 = wk[0], w1 = wk[1];
        float wv[8] = {w0.x, w0.y, w0.z, w0.w, w1.x, w1.y, w1.z, w1.w};
#pragma unroll
        for (int i = 0; i < 4; ++i)
#pragma unroll
            for (int j = 0; j < 8; ++j)
                acc[i][j] += av[i] * wv[j];
    }

#pragma unroll
    for (int i = 0; i < 4; ++i) {
        int row = e0 + tr * 4 + i;
        float r[8];
#pragma unroll
        for (int j = 0; j < 8; ++j) r[j] = lsig(acc[i][j]);
        float4* op = reinterpret_cast<float4*>(out + (size_t)row * 128 + tc * 8);
        op[0] = make_float4(r[0], r[1], r[2], r[3]);
        op[1] = make_float4(r[4], r[5], r[6], r[7]);
    }
}

// ---------------------------------------------------------------------------
extern "C" void kernel_launch(void* const* d_in, const int* in_sizes, int n_in,
                              void* d_out, int out_size) {
    const float* state   = (const float*)d_in[0];
    const float* feature = (const float*)d_in[1];
    const float* mask    = (const float*)d_in[2];
    // d_in[3] = mask_transpose: intentionally unused (saves 268MB of DRAM reads)
    const float* W1m = (const float*)d_in[4];
    const float* b1m = (const float*)d_in[5];
    const float* W2m = (const float*)d_in[6];
    const float* W1a = (const float*)d_in[7];
    const float* b1a = (const float*)d_in[8];
    const float* W2a = (const float*)d_in[9];
    float* out = (float*)d_out;

    const int smem_mlp   = (128 * XS + 128 * WS + 128) * 4;                  // ~101 KB
    const int smem_final = (DCAT * XS + DCAT * WS + 128 * XS + 128) * 4;     // ~156 KB

    cudaFuncSetAttribute((const void*)mlp_kernel<true>,
                         cudaFuncAttributeMaxDynamicSharedMemorySize, smem_mlp);
    cudaFuncSetAttribute((const void*)mlp_kernel<false>,
                         cudaFuncAttributeMaxDynamicSharedMemorySize, smem_mlp);
    cudaFuncSetAttribute((const void*)final_kernel,
                         cudaFuncAttributeMaxDynamicSharedMemorySize, smem_final);

    void *p_h1, *p_s;
    cudaGetSymbolAddress(&p_h1, g_h1);
    cudaGetSymbolAddress(&p_s,  g_s);

    zero_kernel<<<(E_TOT + 255) / 256, 256>>>();
    mlp_kernel<true ><<<E_TOT / 64, 256, smem_mlp>>>(state, W1m, b1m, (float*)p_h1);
    mlp_kernel<false><<<E_TOT / 64, 256, smem_mlp>>>((const float*)p_h1, W2m, nullptr, (float*)p_s);
    scan_kernel<<<N_NODES, 128>>>(mask);
    final_kernel<<<E_TOT / 64, 256, smem_final>>>(feature, W1a, b1a, W2a, out);
}

// round 2
// speedup vs baseline: 1.2437x; 1.2437x over previous
#include <cuda_runtime.h>
#include <cstdint>

// Problem constants
#define E_TOT   32768
#define N_NODES 2048
#define D       128
#define DF      32
#define DCAT    160
#define MAXED   64

// smem strides (floats)
#define XS 65
#define WS 132

// Scratch (__device__ globals: allocation-free rule)
__device__ float g_s [(size_t)E_TOT * D];
__device__ float g_node[(size_t)N_NODES * D];
__device__ int   g_edeg[E_TOT];
__device__ int   g_enode[(size_t)E_TOT * MAXED];

__device__ __forceinline__ float lsig(float x) {
    return fminf(x, 0.0f) - log1pf(__expf(-fabsf(x)));
}

// Packed dual-FMA: d = a*b + d on two fp32 lanes in one FFMA2 issue slot.
__device__ __forceinline__ void ffma2(float2& d, const float2 a, const float2 b) {
    asm("fma.rn.f32x2 %0, %1, %2, %0;"
        : "+l"(*reinterpret_cast<unsigned long long*>(&d))
        : "l"(*reinterpret_cast<const unsigned long long*>(&a)),
          "l"(*reinterpret_cast<const unsigned long long*>(&b)));
}

__global__ void zero_kernel() {
    int i = blockIdx.x * blockDim.x + threadIdx.x;
    if (i < E_TOT) g_edeg[i] = 0;
}

// ---------------------------------------------------------------------------
// GEMM inner step: 4x8 micro-tile as 4x4 float2 accumulators, 16 FFMA2/k.
// ---------------------------------------------------------------------------
#define GEMM_STEP(XBASE, ACC)                                                  \
    {                                                                          \
        const float* xk = (XBASE);                                             \
        float2 a2_0 = make_float2(xk[0], xk[0]);                               \
        float2 a2_1 = make_float2(xk[1], xk[1]);                               \
        float2 a2_2 = make_float2(xk[2], xk[2]);                               \
        float2 a2_3 = make_float2(xk[3], xk[3]);                               \
        float4 w0 = wk[0], w1 = wk[1];                                         \
        float2 wp0 = make_float2(w0.x, w0.y);                                  \
        float2 wp1 = make_float2(w0.z, w0.w);                                  \
        float2 wp2 = make_float2(w1.x, w1.y);                                  \
        float2 wp3 = make_float2(w1.z, w1.w);                                  \
        ffma2(ACC[0][0], a2_0, wp0); ffma2(ACC[0][1], a2_0, wp1);              \
        ffma2(ACC[0][2], a2_0, wp2); ffma2(ACC[0][3], a2_0, wp3);              \
        ffma2(ACC[1][0], a2_1, wp0); ffma2(ACC[1][1], a2_1, wp1);              \
        ffma2(ACC[1][2], a2_1, wp2); ffma2(ACC[1][3], a2_1, wp3);              \
        ffma2(ACC[2][0], a2_2, wp0); ffma2(ACC[2][1], a2_2, wp1);              \
        ffma2(ACC[2][2], a2_2, wp2); ffma2(ACC[2][3], a2_2, wp3);              \
        ffma2(ACC[3][0], a2_3, wp0); ffma2(ACC[3][1], a2_3, wp1);              \
        ffma2(ACC[3][2], a2_3, wp2); ffma2(ACC[3][3], a2_3, wp3);              \
    }

// ---------------------------------------------------------------------------
// Fused memory MLP: g_s = ls( ls(state @ W1m^T + b1m) @ W2m^T )
// Block: 64 rows x 128 cols, 256 threads. h1 never leaves shared memory.
// ---------------------------------------------------------------------------
__global__ void __launch_bounds__(256) mem_mlp_kernel(const float* __restrict__ state,
                                                      const float* __restrict__ W1m,
                                                      const float* __restrict__ b1m,
                                                      const float* __restrict__ W2m,
                                                      float* __restrict__ sout) {
    extern __shared__ float sm[];
    float* xT = sm;              // [128][XS]  k-major x / later h
    float* wT = xT + 128 * XS;   // [128][WS]  W1m then W2m
    float* sb = wT + 128 * WS;   // [128] bias

    const int tid = threadIdx.x;
    const int e0  = blockIdx.x * 64;

    const float* inb = state + (size_t)e0 * 128;
    for (int idx = tid; idx < 64 * 128; idx += 256) {
        int m = idx >> 7, k = idx & 127;
        xT[k * XS + m] = inb[idx];
    }
    for (int idx = tid; idx < 128 * 128; idx += 256) {
        int n = idx >> 7, k = idx & 127;
        wT[k * WS + n] = W1m[idx];
    }
    if (tid < 128) sb[tid] = b1m[tid];
    __syncthreads();

    const int tr = tid >> 4, tc = tid & 15;
    float2 acc[4][4];
#pragma unroll
    for (int i = 0; i < 4; ++i)
#pragma unroll
        for (int j = 0; j < 4; ++j) acc[i][j] = make_float2(0.f, 0.f);

#pragma unroll 8
    for (int k = 0; k < 128; ++k) {
        const float4* wk = reinterpret_cast<const float4*>(wT + k * WS) + tc * 2;
        GEMM_STEP(xT + k * XS + tr * 4, acc)
    }

    // h = ls(acc + b) into registers, then recycle xT
    float h[4][8];
#pragma unroll
    for (int i = 0; i < 4; ++i)
#pragma unroll
        for (int j = 0; j < 4; ++j) {
            int col = tc * 8 + j * 2;
            h[i][j * 2]     = lsig(acc[i][j].x + sb[col]);
            h[i][j * 2 + 1] = lsig(acc[i][j].y + sb[col + 1]);
        }
    __syncthreads();     // all xT/wT reads complete
#pragma unroll
    for (int i = 0; i < 4; ++i)
#pragma unroll
        for (int j = 0; j < 8; ++j)
            xT[(tc * 8 + j) * XS + tr * 4 + i] = h[i][j];
    for (int idx = tid; idx < 128 * 128; idx += 256) {
        int n = idx >> 7, k = idx & 127;
        wT[k * WS + n] = W2m[idx];
    }
    __syncthreads();

#pragma unroll
    for (int i = 0; i < 4; ++i)
#pragma unroll
        for (int j = 0; j < 4; ++j) acc[i][j] = make_float2(0.f, 0.f);

#pragma unroll 8
    for (int k = 0; k < 128; ++k) {
        const float4* wk = reinterpret_cast<const float4*>(wT + k * WS) + tc * 2;
        GEMM_STEP(xT + k * XS + tr * 4, acc)
    }

#pragma unroll
    for (int i = 0; i < 4; ++i) {
        int row = e0 + tr * 4 + i;
        float r[8];
#pragma unroll
        for (int j = 0; j < 4; ++j) {
            r[j * 2]     = lsig(acc[i][j].x);
            r[j * 2 + 1] = lsig(acc[i][j].y);
        }
        float4* op = reinterpret_cast<float4*>(sout + (size_t)row * 128 + tc * 8);
        op[0] = make_float4(r[0], r[1], r[2], r[3]);
        op[1] = make_float4(r[4], r[5], r[6], r[7]);
    }
}

// ---------------------------------------------------------------------------
// Mask scan: 2048-edge chunks, MLP=4 streaming mask loads, 16 sync rounds.
// ---------------------------------------------------------------------------
__global__ void __launch_bounds__(128) scan_kernel(const float* __restrict__ mask) {
    const int n = blockIdx.x;
    const int t = threadIdx.x;
    __shared__ int s_cnt;
    __shared__ int s_list[512];

    const float4* mrow = reinterpret_cast<const float4*>(mask + (size_t)n * E_TOT);
    float acc = 0.0f;

    for (int base = 0; base < E_TOT; base += 2048) {
        if (t == 0) s_cnt = 0;
        __syncthreads();
        const int fb = base >> 2;
        float4 mv[4];
#pragma unroll
        for (int q = 0; q < 4; ++q) mv[q] = __ldcs(&mrow[fb + q * 128 + t]);
#pragma unroll
        for (int q = 0; q < 4; ++q) {
            int e0 = base + q * 512 + t * 4;
            if (mv[q].x != 0.0f) s_list[atomicAdd(&s_cnt, 1)] = e0;
            if (mv[q].y != 0.0f) s_list[atomicAdd(&s_cnt, 1)] = e0 + 1;
            if (mv[q].z != 0.0f) s_list[atomicAdd(&s_cnt, 1)] = e0 + 2;
            if (mv[q].w != 0.0f) s_list[atomicAdd(&s_cnt, 1)] = e0 + 3;
        }
        __syncthreads();
        int c = min(s_cnt, 512);
        float a0 = 0.f, a1 = 0.f, a2 = 0.f, a3 = 0.f;
        int i = 0;
        for (; i + 4 <= c; i += 4) {
            a0 += g_s[(size_t)s_list[i]     * 128 + t];
            a1 += g_s[(size_t)s_list[i + 1] * 128 + t];
            a2 += g_s[(size_t)s_list[i + 2] * 128 + t];
            a3 += g_s[(size_t)s_list[i + 3] * 128 + t];
        }
        for (; i < c; ++i) a0 += g_s[(size_t)s_list[i] * 128 + t];
        acc += (a0 + a1) + (a2 + a3);
        for (i = t; i < c; i += 128) {
            int e = s_list[i];
            int p = atomicAdd(&g_edeg[e], 1);
            if (p < MAXED) g_enode[(size_t)e * MAXED + p] = n;
        }
        __syncthreads();
    }
    g_node[(size_t)n * 128 + t] = acc;
}

// ---------------------------------------------------------------------------
// Fused final stage: cat = [maskT@node - s, feature]; out = ls(ls(cat W1a^T+b) W2a^T)
// xT region is recycled for the hidden tile after GEMM1.
// ---------------------------------------------------------------------------
__global__ void __launch_bounds__(256) final_kernel(const float* __restrict__ feature,
                                                    const float* __restrict__ W1a,
                                                    const float* __restrict__ b1a,
                                                    const float* __restrict__ W2a,
                                                    float* __restrict__ out) {
    extern __shared__ float sm[];
    float* xT = sm;                   // [160][XS] cat tile, later [128][XS] hidden
    float* wT = xT + DCAT * XS;       // [160][WS] W1a then W2a
    float* sb = wT + DCAT * WS;       // [128]

    const int tid = threadIdx.x;
    const int e0  = blockIdx.x * 64;

    // agg part: 4 threads per edge, 32-dim slab each
    {
        int m  = tid >> 2;
        int kb = (tid & 3) << 5;
        int e  = e0 + m;
        float v[32];
        const float4* sp = reinterpret_cast<const float4*>(g_s + (size_t)e * 128 + kb);
#pragma unroll
        for (int q = 0; q < 8; ++q) {
            float4 f = sp[q];
            v[q * 4 + 0] = -f.x; v[q * 4 + 1] = -f.y;
            v[q * 4 + 2] = -f.z; v[q * 4 + 3] = -f.w;
        }
        int d = g_edeg[e];
        if (d > MAXED) d = MAXED;
        for (int i = 0; i < d; ++i) {
            int nn = g_enode[(size_t)e * MAXED + i];
            const float4* np = reinterpret_cast<const float4*>(g_node + (size_t)nn * 128 + kb);
#pragma unroll
            for (int q = 0; q < 8; ++q) {
                float4 f = np[q];
                v[q * 4 + 0] += f.x; v[q * 4 + 1] += f.y;
                v[q * 4 + 2] += f.z; v[q * 4 + 3] += f.w;
            }
        }
#pragma unroll
        for (int kk = 0; kk < 32; ++kk) xT[(kb + kk) * XS + m] = v[kk];
    }
    for (int idx = tid; idx < 64 * DF; idx += 256) {
        int m = idx >> 5, k = idx & 31;
        xT[(128 + k) * XS + m] = feature[(size_t)(e0 + m) * DF + k];
    }
    for (int idx = tid; idx < 128 * DCAT; idx += 256) {
        int n = idx / DCAT, k = idx - n * DCAT;
        wT[k * WS + n] = W1a[idx];
    }
    if (tid < 128) sb[tid] = b1a[tid];
    __syncthreads();

    const int tr = tid >> 4, tc = tid & 15;
    float2 acc[4][4];
#pragma unroll
    for (int i = 0; i < 4; ++i)
#pragma unroll
        for (int j = 0; j < 4; ++j) acc[i][j] = make_float2(0.f, 0.f);

#pragma unroll 8
    for (int k = 0; k < DCAT; ++k) {
        const float4* wk = reinterpret_cast<const float4*>(wT + k * WS) + tc * 2;
        GEMM_STEP(xT + k * XS + tr * 4, acc)
    }

    float h[4][8];
#pragma unroll
    for (int i = 0; i < 4; ++i)
#pragma unroll
        for (int j = 0; j < 4; ++j) {
            int col = tc * 8 + j * 2;
            h[i][j * 2]     = lsig(acc[i][j].x + sb[col]);
            h[i][j * 2 + 1] = lsig(acc[i][j].y + sb[col + 1]);
        }
    __syncthreads();
#pragma unroll
    for (int i = 0; i < 4; ++i)
#pragma unroll
        for (int j = 0; j < 8; ++j)
            xT[(tc * 8 + j) * XS + tr * 4 + i] = h[i][j];
    for (int idx = tid; idx < 128 * 128; idx += 256) {
        int n = idx >> 7, k = idx & 127;
        wT[k * WS + n] = W2a[idx];
    }
    __syncthreads();

#pragma unroll
    for (int i = 0; i < 4; ++i)
#pragma unroll
        for (int j = 0; j < 4; ++j) acc[i][j] = make_float2(0.f, 0.f);

#pragma unroll 8
    for (int k = 0; k < 128; ++k) {
        const float4* wk = reinterpret_cast<const float4*>(wT + k * WS) + tc * 2;
        GEMM_STEP(xT + k * XS + tr * 4, acc)
    }

#pragma unroll
    for (int i = 0; i < 4; ++i) {
        int row = e0 + tr * 4 + i;
        float r[8];
#pragma unroll
        for (int j = 0; j < 4; ++j) {
            r[j * 2]     = lsig(acc[i][j].x);
            r[j * 2 + 1] = lsig(acc[i][j].y);
        }
        float4* op = reinterpret_cast<float4*>(out + (size_t)row * 128 + tc * 8);
        op[0] = make_float4(r[0], r[1], r[2], r[3]);
        op[1] = make_float4(r[4], r[5], r[6], r[7]);
    }
}

// ---------------------------------------------------------------------------
extern "C" void kernel_launch(void* const* d_in, const int* in_sizes, int n_in,
                              void* d_out, int out_size) {
    const float* state   = (const float*)d_in[0];
    const float* feature = (const float*)d_in[1];
    const float* mask    = (const float*)d_in[2];
    // d_in[3] mask_transpose unused
    const float* W1m = (const float*)d_in[4];
    const float* b1m = (const float*)d_in[5];
    const float* W2m = (const float*)d_in[6];
    const float* W1a = (const float*)d_in[7];
    const float* b1a = (const float*)d_in[8];
    const float* W2a = (const float*)d_in[9];
    float* out = (float*)d_out;

    const int smem_mem   = (128 * XS + 128 * WS + 128) * 4;   // ~101 KB
    const int smem_final = (DCAT * XS + DCAT * WS + 128) * 4; // ~127 KB

    cudaFuncSetAttribute((const void*)mem_mlp_kernel,
                         cudaFuncAttributeMaxDynamicSharedMemorySize, smem_mem);
    cudaFuncSetAttribute((const void*)final_kernel,
                         cudaFuncAttributeMaxDynamicSharedMemorySize, smem_final);

    void* p_s;
    cudaGetSymbolAddress(&p_s, g_s);

    zero_kernel<<<(E_TOT + 255) / 256, 256>>>();
    mem_mlp_kernel<<<E_TOT / 64, 256, smem_mem>>>(state, W1m, b1m, W2m, (float*)p_s);
    scan_kernel<<<N_NODES, 128>>>(mask);
    final_kernel<<<E_TOT / 64, 256, smem_final>>>(feature, W1a, b1a, W2a, out);
}

// round 7
// speedup vs baseline: 1.2963x; 1.0423x over previous
#include <cuda_runtime.h>
#include <cstdint>

#define E_TOT   32768
#define N_NODES 2048
#define D       128
#define DF      32
#define DCAT    160
#define MAXED   64
#define XS      65     // smem x-tile stride: conflict-free transpose fill + broadcast reads

// Scratch (__device__ globals: allocation-free rule)
__device__ float g_s [(size_t)E_TOT * D];
__device__ float g_node[(size_t)N_NODES * D];
__device__ int   g_edeg[E_TOT];
__device__ int   g_enode[(size_t)E_TOT * MAXED];
// Pre-transposed weights (k-major), read via __ldg in GEMM inner loops
__device__ float g_w1mT[D * D];
__device__ float g_w2mT[D * D];
__device__ float g_w1aT[DCAT * D];
__device__ float g_w2aT[D * D];

__device__ __forceinline__ float lsig(float x) {
    return fminf(x, 0.0f) - log1pf(__expf(-fabsf(x)));
}

// Packed dual-FMA (sm_103a FFMA2): d = a*b + d on two fp32 lanes per issue slot.
__device__ __forceinline__ void ffma2(float2& d, const float2 a, const float2 b) {
    asm("fma.rn.f32x2 %0, %1, %2, %0;"
        : "+l"(*reinterpret_cast<unsigned long long*>(&d))
        : "l"(*reinterpret_cast<const unsigned long long*>(&a)),
          "l"(*reinterpret_cast<const unsigned long long*>(&b)));
}

__global__ void zero_kernel() {
    int i = blockIdx.x * blockDim.x + threadIdx.x;
    if (i < E_TOT) g_edeg[i] = 0;
}

// One-shot weight transpose into k-major gmem buffers.
__global__ void wtrans_kernel(const float* __restrict__ W1m, const float* __restrict__ W2m,
                              const float* __restrict__ W1a, const float* __restrict__ W2a) {
    int i = blockIdx.x * blockDim.x + threadIdx.x;
    if (i < 16384) {                     // W1m [128][128]
        int r = i >> 7, c = i & 127;
        g_w1mT[c * 128 + r] = W1m[i];
    } else if (i < 32768) {              // W2m [128][128]
        int j = i - 16384; int r = j >> 7, c = j & 127;
        g_w2mT[c * 128 + r] = W2m[j];
    } else if (i < 53248) {              // W1a [128][160]
        int j = i - 32768; int r = j / 160, c = j - r * 160;
        g_w1aT[c * 128 + r] = W1a[j];
    } else if (i < 69632) {              // W2a [128][128]
        int j = i - 53248; int r = j >> 7, c = j & 127;
        g_w2aT[c * 128 + r] = W2a[j];
    }
}

// ---------------------------------------------------------------------------
// GEMM inner step: weights streamed from gmem (L1-resident), x from smem.
// 4x8 micro-tile = 4x4 float2 accumulators, 16 FFMA2 per k.
// Macro locals prefixed with _ to avoid shadowing caller identifiers.
// ---------------------------------------------------------------------------
#define GEMM_K_STEP(XK, WK, ACC)                                               \
    {                                                                          \
        const float4* _wkp = (WK);                                             \
        float4 _w0 = __ldg(_wkp), _w1 = __ldg(_wkp + 1);                       \
        const float* _xk = (XK);                                               \
        float2 _a0 = make_float2(_xk[0], _xk[0]);                              \
        float2 _a1 = make_float2(_xk[1], _xk[1]);                              \
        float2 _a2 = make_float2(_xk[2], _xk[2]);                              \
        float2 _a3 = make_float2(_xk[3], _xk[3]);                              \
        float2 _p0 = make_float2(_w0.x, _w0.y);                                \
        float2 _p1 = make_float2(_w0.z, _w0.w);                                \
        float2 _p2 = make_float2(_w1.x, _w1.y);                                \
        float2 _p3 = make_float2(_w1.z, _w1.w);                                \
        ffma2(ACC[0][0], _a0, _p0); ffma2(ACC[0][1], _a0, _p1);                \
        ffma2(ACC[0][2], _a0, _p2); ffma2(ACC[0][3], _a0, _p3);                \
        ffma2(ACC[1][0], _a1, _p0); ffma2(ACC[1][1], _a1, _p1);                \
        ffma2(ACC[1][2], _a1, _p2); ffma2(ACC[1][3], _a1, _p3);                \
        ffma2(ACC[2][0], _a2, _p0); ffma2(ACC[2][1], _a2, _p1);                \
        ffma2(ACC[2][2], _a2, _p2); ffma2(ACC[2][3], _a2, _p3);                \
        ffma2(ACC[3][0], _a3, _p0); ffma2(ACC[3][1], _a3, _p1);                \
        ffma2(ACC[3][2], _a3, _p2); ffma2(ACC[3][3], _a3, _p3);                \
    }

#define ACC_CLEAR(ACC)                                                         \
    _Pragma("unroll") for (int i = 0; i < 4; ++i)                              \
    _Pragma("unroll") for (int j = 0; j < 4; ++j) ACC[i][j] = make_float2(0.f, 0.f);

// ---------------------------------------------------------------------------
// Fused memory MLP: g_s = ls( ls(state @ W1m^T + b1m) @ W2m^T )
// smem = x-tile only (34KB) -> 2 CTAs/SM, 128 regs/thread budget.
// ---------------------------------------------------------------------------
__global__ void __launch_bounds__(256, 2) mem_mlp_kernel(const float* __restrict__ state,
                                                         const float* __restrict__ b1m,
                                                         float* __restrict__ sout) {
    extern __shared__ float sm[];
    float* xT = sm;              // [128][XS] k-major x, recycled for h
    float* sb = xT + 128 * XS;   // [128] bias

    const int tid = threadIdx.x;
    const int e0  = blockIdx.x * 64;

    const float* inb = state + (size_t)e0 * 128;
    for (int idx = tid; idx < 64 * 128; idx += 256) {
        int m = idx >> 7, k = idx & 127;
        xT[k * XS + m] = inb[idx];
    }
    if (tid < 128) sb[tid] = b1m[tid];
    __syncthreads();

    const int tr = tid >> 4, tc = tid & 15;
    float2 acc[4][4];
    ACC_CLEAR(acc)

    const float4* wp1_ = reinterpret_cast<const float4*>(g_w1mT) + tc * 2;
#pragma unroll 4
    for (int k = 0; k < 128; ++k)
        GEMM_K_STEP(xT + k * XS + tr * 4, wp1_ + k * 32, acc)

    float h[4][8];
#pragma unroll
    for (int i = 0; i < 4; ++i)
#pragma unroll
        for (int j = 0; j < 4; ++j) {
            int col = tc * 8 + j * 2;
            h[i][j * 2]     = lsig(acc[i][j].x + sb[col]);
            h[i][j * 2 + 1] = lsig(acc[i][j].y + sb[col + 1]);
        }
    __syncthreads();
#pragma unroll
    for (int i = 0; i < 4; ++i)
#pragma unroll
        for (int j = 0; j < 8; ++j)
            xT[(tc * 8 + j) * XS + tr * 4 + i] = h[i][j];
    __syncthreads();

    ACC_CLEAR(acc)
    const float4* wp2_ = reinterpret_cast<const float4*>(g_w2mT) + tc * 2;
#pragma unroll 4
    for (int k = 0; k < 128; ++k)
        GEMM_K_STEP(xT + k * XS + tr * 4, wp2_ + k * 32, acc)

#pragma unroll
    for (int i = 0; i < 4; ++i) {
        int row = e0 + tr * 4 + i;
        float r[8];
#pragma unroll
        for (int j = 0; j < 4; ++j) {
            r[j * 2]     = lsig(acc[i][j].x);
            r[j * 2 + 1] = lsig(acc[i][j].y);
        }
        float4* op = reinterpret_cast<float4*>(sout + (size_t)row * 128 + tc * 8);
        op[0] = make_float4(r[0], r[1], r[2], r[3]);
        op[1] = make_float4(r[4], r[5], r[6], r[7]);
    }
}

// ---------------------------------------------------------------------------
// Mask scan with software pipelining: prefetch next mask chunk (DRAM) before
// the g_s gather (L2) so the two latency classes overlap.
// ---------------------------------------------------------------------------
__global__ void __launch_bounds__(128) scan_kernel(const float* __restrict__ mask) {
    const int n = blockIdx.x;
    const int t = threadIdx.x;
    __shared__ int s_cnt;
    __shared__ int s_list[512];

    const float4* mrow = reinterpret_cast<const float4*>(mask + (size_t)n * E_TOT);
    float acc = 0.0f;

    float4 mv[4];
#pragma unroll
    for (int q = 0; q < 4; ++q) mv[q] = __ldcs(&mrow[q * 128 + t]);

    for (int base = 0; base < E_TOT; base += 2048) {
        if (t == 0) s_cnt = 0;
        __syncthreads();
#pragma unroll
        for (int q = 0; q < 4; ++q) {
            int e0 = base + q * 512 + t * 4;
            if (mv[q].x != 0.0f) s_list[atomicAdd(&s_cnt, 1)] = e0;
            if (mv[q].y != 0.0f) s_list[atomicAdd(&s_cnt, 1)] = e0 + 1;
            if (mv[q].z != 0.0f) s_list[atomicAdd(&s_cnt, 1)] = e0 + 2;
            if (mv[q].w != 0.0f) s_list[atomicAdd(&s_cnt, 1)] = e0 + 3;
        }
        __syncthreads();

        // prefetch next chunk (in flight across the gather below)
        float4 nv[4] = {mv[0], mv[1], mv[2], mv[3]};
        if (base + 2048 < E_TOT) {
            int fb = (base + 2048) >> 2;
#pragma unroll
            for (int q = 0; q < 4; ++q) nv[q] = __ldcs(&mrow[fb + q * 128 + t]);
        }

        int c = min(s_cnt, 512);
        float a0 = 0.f, a1 = 0.f, a2 = 0.f, a3 = 0.f;
        int i = 0;
        for (; i + 4 <= c; i += 4) {
            a0 += g_s[(size_t)s_list[i]     * 128 + t];
            a1 += g_s[(size_t)s_list[i + 1] * 128 + t];
            a2 += g_s[(size_t)s_list[i + 2] * 128 + t];
            a3 += g_s[(size_t)s_list[i + 3] * 128 + t];
        }
        for (; i < c; ++i) a0 += g_s[(size_t)s_list[i] * 128 + t];
        acc += (a0 + a1) + (a2 + a3);
        for (i = t; i < c; i += 128) {
            int e = s_list[i];
            int p = atomicAdd(&g_edeg[e], 1);
            if (p < MAXED) g_enode[(size_t)e * MAXED + p] = n;
        }
        __syncthreads();
#pragma unroll
        for (int q = 0; q < 4; ++q) mv[q] = nv[q];
    }
    g_node[(size_t)n * 128 + t] = acc;
}

// ---------------------------------------------------------------------------
// Fused final stage: cat = [maskT@node - s, feature]; out = ls(ls(cat W1a^T+b) W2a^T)
// smem = cat tile only (42KB).
// ---------------------------------------------------------------------------
__global__ void __launch_bounds__(256, 2) final_kernel(const float* __restrict__ feature,
                                                       const float* __restrict__ b1a,
                                                       float* __restrict__ out) {
    extern __shared__ float sm[];
    float* xT = sm;                   // [160][XS] cat tile; rows 0..127 recycled for h
    float* sb = xT + DCAT * XS;       // [128]

    const int tid = threadIdx.x;
    const int e0  = blockIdx.x * 64;

    // agg part: 4 threads per edge, 32-dim slab each
    {
        int m  = tid >> 2;
        int kb = (tid & 3) << 5;
        int e  = e0 + m;
        float v[32];
        const float4* sp = reinterpret_cast<const float4*>(g_s + (size_t)e * 128 + kb);
#pragma unroll
        for (int q = 0; q < 8; ++q) {
            float4 f = sp[q];
            v[q * 4 + 0] = -f.x; v[q * 4 + 1] = -f.y;
            v[q * 4 + 2] = -f.z; v[q * 4 + 3] = -f.w;
        }
        int d = g_edeg[e];
        if (d > MAXED) d = MAXED;
        for (int i = 0; i < d; ++i) {
            int nn = g_enode[(size_t)e * MAXED + i];
            const float4* np = reinterpret_cast<const float4*>(g_node + (size_t)nn * 128 + kb);
#pragma unroll
            for (int q = 0; q < 8; ++q) {
                float4 f = np[q];
                v[q * 4 + 0] += f.x; v[q * 4 + 1] += f.y;
                v[q * 4 + 2] += f.z; v[q * 4 + 3] += f.w;
            }
        }
#pragma unroll
        for (int kk = 0; kk < 32; ++kk) xT[(kb + kk) * XS + m] = v[kk];
    }
    for (int idx = tid; idx < 64 * DF; idx += 256) {
        int m = idx >> 5, k = idx & 31;
        xT[(128 + k) * XS + m] = feature[(size_t)(e0 + m) * DF + k];
    }
    if (tid < 128) sb[tid] = b1a[tid];
    __syncthreads();

    const int tr = tid >> 4, tc = tid & 15;
    float2 acc[4][4];
    ACC_CLEAR(acc)

    const float4* wp1_ = reinterpret_cast<const float4*>(g_w1aT) + tc * 2;
#pragma unroll 4
    for (int k = 0; k < DCAT; ++k)
        GEMM_K_STEP(xT + k * XS + tr * 4, wp1_ + k * 32, acc)

    float h[4][8];
#pragma unroll
    for (int i = 0; i < 4; ++i)
#pragma unroll
        for (int j = 0; j < 4; ++j) {
            int col = tc * 8 + j * 2;
            h[i][j * 2]     = lsig(acc[i][j].x + sb[col]);
            h[i][j * 2 + 1] = lsig(acc[i][j].y + sb[col + 1]);
        }
    __syncthreads();
#pragma unroll
    for (int i = 0; i < 4; ++i)
#pragma unroll
        for (int j = 0; j < 8; ++j)
            xT[(tc * 8 + j) * XS + tr * 4 + i] = h[i][j];
    __syncthreads();

    ACC_CLEAR(acc)
    const float4* wp2_ = reinterpret_cast<const float4*>(g_w2aT) + tc * 2;
#pragma unroll 4
    for (int k = 0; k < 128; ++k)
        GEMM_K_STEP(xT + k * XS + tr * 4, wp2_ + k * 32, acc)

#pragma unroll
    for (int i = 0; i < 4; ++i) {
        int row = e0 + tr * 4 + i;
        float r[8];
#pragma unroll
        for (int j = 0; j < 4; ++j) {
            r[j * 2]     = lsig(acc[i][j].x);
            r[j * 2 + 1] = lsig(acc[i][j].y);
        }
        float4* op = reinterpret_cast<float4*>(out + (size_t)row * 128 + tc * 8);
        op[0] = make_float4(r[0], r[1], r[2], r[3]);
        op[1] = make_float4(r[4], r[5], r[6], r[7]);
    }
}

// ---------------------------------------------------------------------------
extern "C" void kernel_launch(void* const* d_in, const int* in_sizes, int n_in,
                              void* d_out, int out_size) {
    const float* state   = (const float*)d_in[0];
    const float* feature = (const float*)d_in[1];
    const float* mask    = (const float*)d_in[2];
    // d_in[3] mask_transpose unused
    const float* W1m = (const float*)d_in[4];
    const float* b1m = (const float*)d_in[5];
    const float* W2m = (const float*)d_in[6];
    const float* W1a = (const float*)d_in[7];
    const float* b1a = (const float*)d_in[8];
    const float* W2a = (const float*)d_in[9];
    float* out = (float*)d_out;

    const int smem_mem   = (128 * XS + 128) * 4;   // ~33.8 KB
    const int smem_final = (DCAT * XS + 128) * 4;  // ~42.1 KB

    cudaFuncSetAttribute((const void*)mem_mlp_kernel,
                         cudaFuncAttributeMaxDynamicSharedMemorySize, smem_mem);
    cudaFuncSetAttribute((const void*)final_kernel,
                         cudaFuncAttributeMaxDynamicSharedMemorySize, smem_final);

    void* p_s;
    cudaGetSymbolAddress(&p_s, g_s);

    zero_kernel<<<(E_TOT + 255) / 256, 256>>>();
    wtrans_kernel<<<(69632 + 255) / 256, 256>>>(W1m, W2m, W1a, W2a);
    mem_mlp_kernel<<<E_TOT / 64, 256, smem_mem>>>(state, b1m, (float*)p_s);
    scan_kernel<<<N_NODES, 128>>>(mask);
    final_kernel<<<E_TOT / 64, 256, smem_final>>>(feature, b1a, out);
}

// round 8
// speedup vs baseline: 1.3182x; 1.0168x over previous
#include <cuda_runtime.h>
#include <cstdint>

#define E_TOT   32768
#define N_NODES 2048
#define D       128
#define DF      32
#define DCAT    160
#define MAXED   64     // nodes per edge cap (mean ~10.2)
#define MAXNE   256    // edges per node cap (mean ~164, +7 sigma safe)
#define XS      65     // smem x-tile stride

// Scratch (__device__ globals: allocation-free rule)
__device__ float g_s [(size_t)E_TOT * D];
__device__ float g_node[(size_t)N_NODES * D];
__device__ int   g_edeg[E_TOT];
__device__ int   g_enode[(size_t)E_TOT * MAXED];
__device__ int   g_ncnt[N_NODES];
__device__ int   g_nlist[(size_t)N_NODES * MAXNE];
// Pre-transposed weights (k-major)
__device__ float g_w1mT[D * D];
__device__ float g_w2mT[D * D];
__device__ float g_w1aT[DCAT * D];
__device__ float g_w2aT[D * D];

__device__ __forceinline__ float lsig(float x) {
    return fminf(x, 0.0f) - log1pf(__expf(-fabsf(x)));
}

// Packed dual-FMA (sm_103a FFMA2)
__device__ __forceinline__ void ffma2(float2& d, const float2 a, const float2 b) {
    asm("fma.rn.f32x2 %0, %1, %2, %0;"
        : "+l"(*reinterpret_cast<unsigned long long*>(&d))
        : "l"(*reinterpret_cast<const unsigned long long*>(&a)),
          "l"(*reinterpret_cast<const unsigned long long*>(&b)));
}

__global__ void zero_kernel() {
    int i = blockIdx.x * blockDim.x + threadIdx.x;
    if (i < E_TOT) g_edeg[i] = 0;
    if (i < N_NODES) g_ncnt[i] = 0;
}

__global__ void wtrans_kernel(const float* __restrict__ W1m, const float* __restrict__ W2m,
                              const float* __restrict__ W1a, const float* __restrict__ W2a) {
    int i = blockIdx.x * blockDim.x + threadIdx.x;
    if (i < 16384) {
        int r = i >> 7, c = i & 127;
        g_w1mT[c * 128 + r] = W1m[i];
    } else if (i < 32768) {
        int j = i - 16384; int r = j >> 7, c = j & 127;
        g_w2mT[c * 128 + r] = W2m[j];
    } else if (i < 53248) {
        int j = i - 32768; int r = j / 160, c = j - r * 160;
        g_w1aT[c * 128 + r] = W1a[j];
    } else if (i < 69632) {
        int j = i - 53248; int r = j >> 7, c = j & 127;
        g_w2aT[c * 128 + r] = W2a[j];
    }
}

// ---------------------------------------------------------------------------
// GEMM inner step (macro locals underscored to avoid capture)
// ---------------------------------------------------------------------------
#define GEMM_K_STEP(XK, WK, ACC)                                               \
    {                                                                          \
        const float4* _wkp = (WK);                                             \
        float4 _w0 = __ldg(_wkp), _w1 = __ldg(_wkp + 1);                       \
        const float* _xk = (XK);                                               \
        float2 _a0 = make_float2(_xk[0], _xk[0]);                              \
        float2 _a1 = make_float2(_xk[1], _xk[1]);                              \
        float2 _a2 = make_float2(_xk[2], _xk[2]);                              \
        float2 _a3 = make_float2(_xk[3], _xk[3]);                              \
        float2 _p0 = make_float2(_w0.x, _w0.y);                                \
        float2 _p1 = make_float2(_w0.z, _w0.w);                                \
        float2 _p2 = make_float2(_w1.x, _w1.y);                                \
        float2 _p3 = make_float2(_w1.z, _w1.w);                                \
        ffma2(ACC[0][0], _a0, _p0); ffma2(ACC[0][1], _a0, _p1);                \
        ffma2(ACC[0][2], _a0, _p2); ffma2(ACC[0][3], _a0, _p3);                \
        ffma2(ACC[1][0], _a1, _p0); ffma2(ACC[1][1], _a1, _p1);                \
        ffma2(ACC[1][2], _a1, _p2); ffma2(ACC[1][3], _a1, _p3);                \
        ffma2(ACC[2][0], _a2, _p0); ffma2(ACC[2][1], _a2, _p1);                \
        ffma2(ACC[2][2], _a2, _p2); ffma2(ACC[2][3], _a2, _p3);                \
        ffma2(ACC[3][0], _a3, _p0); ffma2(ACC[3][1], _a3, _p1);                \
        ffma2(ACC[3][2], _a3, _p2); ffma2(ACC[3][3], _a3, _p3);                \
    }

#define ACC_CLEAR(ACC)                                                         \
    _Pragma("unroll") for (int i = 0; i < 4; ++i)                              \
    _Pragma("unroll") for (int j = 0; j < 4; ++j) ACC[i][j] = make_float2(0.f, 0.f);

// ---------------------------------------------------------------------------
// Fused memory MLP: g_s = ls( ls(state @ W1m^T + b1m) @ W2m^T )
// ---------------------------------------------------------------------------
__global__ void __launch_bounds__(256, 3) mem_mlp_kernel(const float* __restrict__ state,
                                                         const float* __restrict__ b1m,
                                                         float* __restrict__ sout) {
    extern __shared__ float sm[];
    float* xT = sm;
    float* sb = xT + 128 * XS;

    const int tid = threadIdx.x;
    const int e0  = blockIdx.x * 64;

    const float* inb = state + (size_t)e0 * 128;
    for (int idx = tid; idx < 64 * 128; idx += 256) {
        int m = idx >> 7, k = idx & 127;
        xT[k * XS + m] = inb[idx];
    }
    if (tid < 128) sb[tid] = b1m[tid];
    __syncthreads();

    const int tr = tid >> 4, tc = tid & 15;
    float2 acc[4][4];
    ACC_CLEAR(acc)

    const float4* wp1_ = reinterpret_cast<const float4*>(g_w1mT) + tc * 2;
#pragma unroll 4
    for (int k = 0; k < 128; ++k)
        GEMM_K_STEP(xT + k * XS + tr * 4, wp1_ + k * 32, acc)

    float h[4][8];
#pragma unroll
    for (int i = 0; i < 4; ++i)
#pragma unroll
        for (int j = 0; j < 4; ++j) {
            int col = tc * 8 + j * 2;
            h[i][j * 2]     = lsig(acc[i][j].x + sb[col]);
            h[i][j * 2 + 1] = lsig(acc[i][j].y + sb[col + 1]);
        }
    __syncthreads();
#pragma unroll
    for (int i = 0; i < 4; ++i)
#pragma unroll
        for (int j = 0; j < 8; ++j)
            xT[(tc * 8 + j) * XS + tr * 4 + i] = h[i][j];
    __syncthreads();

    ACC_CLEAR(acc)
    const float4* wp2_ = reinterpret_cast<const float4*>(g_w2mT) + tc * 2;
#pragma unroll 4
    for (int k = 0; k < 128; ++k)
        GEMM_K_STEP(xT + k * XS + tr * 4, wp2_ + k * 32, acc)

#pragma unroll
    for (int i = 0; i < 4; ++i) {
        int row = e0 + tr * 4 + i;
        float r[8];
#pragma unroll
        for (int j = 0; j < 4; ++j) {
            r[j * 2]     = lsig(acc[i][j].x);
            r[j * 2 + 1] = lsig(acc[i][j].y);
        }
        float4* op = reinterpret_cast<float4*>(sout + (size_t)row * 128 + tc * 8);
        op[0] = make_float4(r[0], r[1], r[2], r[3]);
        op[1] = make_float4(r[4], r[5], r[6], r[7]);
    }
}

// ---------------------------------------------------------------------------
// Pure mask scan (runs concurrent with mem_mlp): builds node->edge and
// edge->node lists. 16384 independent blocks, 8 back-to-back float4 loads.
// ---------------------------------------------------------------------------
__global__ void __launch_bounds__(128) scan_lists_kernel(const float* __restrict__ mask) {
    const int n = blockIdx.x;
    const int slice = blockIdx.y;           // 0..7, 4096 edges each
    const int t = threadIdx.x;

    const float4* mrow = reinterpret_cast<const float4*>(mask + (size_t)n * E_TOT)
                         + slice * 1024;
    float4 mv[8];
#pragma unroll
    for (int q = 0; q < 8; ++q) mv[q] = __ldcs(&mrow[q * 128 + t]);

#pragma unroll
    for (int q = 0; q < 8; ++q) {
        int e0 = slice * 4096 + q * 512 + t * 4;
        float vals[4] = {mv[q].x, mv[q].y, mv[q].z, mv[q].w};
#pragma unroll
        for (int u = 0; u < 4; ++u) {
            if (vals[u] != 0.0f) {
                int e = e0 + u;
                int p = atomicAdd(&g_ncnt[n], 1);
                if (p < MAXNE) g_nlist[(size_t)n * MAXNE + p] = e;
                int q2 = atomicAdd(&g_edeg[e], 1);
                if (q2 < MAXED) g_enode[(size_t)e * MAXED + q2] = n;
            }
        }
    }
}

// ---------------------------------------------------------------------------
// Node gather: g_node[n][:] = sum over incident edges of g_s[e][:]  (L2-bound)
// ---------------------------------------------------------------------------
__global__ void __launch_bounds__(128) node_sum_kernel() {
    const int n = blockIdx.x;
    const int t = threadIdx.x;
    int c = g_ncnt[n];
    if (c > MAXNE) c = MAXNE;
    const int* lst = g_nlist + (size_t)n * MAXNE;

    float a0 = 0.f, a1 = 0.f, a2 = 0.f, a3 = 0.f;
    int i = 0;
    for (; i + 4 <= c; i += 4) {
        int e0 = __ldg(lst + i), e1 = __ldg(lst + i + 1);
        int e2 = __ldg(lst + i + 2), e3 = __ldg(lst + i + 3);
        a0 += g_s[(size_t)e0 * 128 + t];
        a1 += g_s[(size_t)e1 * 128 + t];
        a2 += g_s[(size_t)e2 * 128 + t];
        a3 += g_s[(size_t)e3 * 128 + t];
    }
    for (; i < c; ++i) a0 += g_s[(size_t)__ldg(lst + i) * 128 + t];
    g_node[(size_t)n * 128 + t] = (a0 + a1) + (a2 + a3);
}

// ---------------------------------------------------------------------------
// Fused final stage
// ---------------------------------------------------------------------------
__global__ void __launch_bounds__(256, 3) final_kernel(const float* __restrict__ feature,
                                                       const float* __restrict__ b1a,
                                                       float* __restrict__ out) {
    extern __shared__ float sm[];
    float* xT = sm;
    float* sb = xT + DCAT * XS;

    const int tid = threadIdx.x;
    const int e0  = blockIdx.x * 64;

    {
        int m  = tid >> 2;
        int kb = (tid & 3) << 5;
        int e  = e0 + m;
        float v[32];
        const float4* sp = reinterpret_cast<const float4*>(g_s + (size_t)e * 128 + kb);
#pragma unroll
        for (int q = 0; q < 8; ++q) {
            float4 f = sp[q];
            v[q * 4 + 0] = -f.x; v[q * 4 + 1] = -f.y;
            v[q * 4 + 2] = -f.z; v[q * 4 + 3] = -f.w;
        }
        int d = g_edeg[e];
        if (d > MAXED) d = MAXED;
        for (int i = 0; i < d; ++i) {
            int nn = g_enode[(size_t)e * MAXED + i];
            const float4* np = reinterpret_cast<const float4*>(g_node + (size_t)nn * 128 + kb);
#pragma unroll
            for (int q = 0; q < 8; ++q) {
                float4 f = np[q];
                v[q * 4 + 0] += f.x; v[q * 4 + 1] += f.y;
                v[q * 4 + 2] += f.z; v[q * 4 + 3] += f.w;
            }
        }
#pragma unroll
        for (int kk = 0; kk < 32; ++kk) xT[(kb + kk) * XS + m] = v[kk];
    }
    for (int idx = tid; idx < 64 * DF; idx += 256) {
        int m = idx >> 5, k = idx & 31;
        xT[(128 + k) * XS + m] = feature[(size_t)(e0 + m) * DF + k];
    }
    if (tid < 128) sb[tid] = b1a[tid];
    __syncthreads();

    const int tr = tid >> 4, tc = tid & 15;
    float2 acc[4][4];
    ACC_CLEAR(acc)

    const float4* wp1_ = reinterpret_cast<const float4*>(g_w1aT) + tc * 2;
#pragma unroll 4
    for (int k = 0; k < DCAT; ++k)
        GEMM_K_STEP(xT + k * XS + tr * 4, wp1_ + k * 32, acc)

    float h[4][8];
#pragma unroll
    for (int i = 0; i < 4; ++i)
#pragma unroll
        for (int j = 0; j < 4; ++j) {
            int col = tc * 8 + j * 2;
            h[i][j * 2]     = lsig(acc[i][j].x + sb[col]);
            h[i][j * 2 + 1] = lsig(acc[i][j].y + sb[col + 1]);
        }
    __syncthreads();
#pragma unroll
    for (int i = 0; i < 4; ++i)
#pragma unroll
        for (int j = 0; j < 8; ++j)
            xT[(tc * 8 + j) * XS + tr * 4 + i] = h[i][j];
    __syncthreads();

    ACC_CLEAR(acc)
    const float4* wp2_ = reinterpret_cast<const float4*>(g_w2aT) + tc * 2;
#pragma unroll 4
    for (int k = 0; k < 128; ++k)
        GEMM_K_STEP(xT + k * XS + tr * 4, wp2_ + k * 32, acc)

#pragma unroll
    for (int i = 0; i < 4; ++i) {
        int row = e0 + tr * 4 + i;
        float r[8];
#pragma unroll
        for (int j = 0; j < 4; ++j) {
            r[j * 2]     = lsig(acc[i][j].x);
            r[j * 2 + 1] = lsig(acc[i][j].y);
        }
        float4* op = reinterpret_cast<float4*>(out + (size_t)row * 128 + tc * 8);
        op[0] = make_float4(r[0], r[1], r[2], r[3]);
        op[1] = make_float4(r[4], r[5], r[6], r[7]);
    }
}

// ---------------------------------------------------------------------------
extern "C" void kernel_launch(void* const* d_in, const int* in_sizes, int n_in,
                              void* d_out, int out_size) {
    const float* state   = (const float*)d_in[0];
    const float* feature = (const float*)d_in[1];
    const float* mask    = (const float*)d_in[2];
    const float* W1m = (const float*)d_in[4];
    const float* b1m = (const float*)d_in[5];
    const float* W2m = (const float*)d_in[6];
    const float* W1a = (const float*)d_in[7];
    const float* b1a = (const float*)d_in[8];
    const float* W2a = (const float*)d_in[9];
    float* out = (float*)d_out;

    const int smem_mem   = (128 * XS + 128) * 4;   // ~33.8 KB
    const int smem_final = (DCAT * XS + 128) * 4;  // ~42.1 KB

    // One-time infra (host-side only; no device allocation)
    static cudaStream_t s_aux = nullptr;
    static cudaEvent_t ev_fork = nullptr, ev_scan = nullptr;
    if (s_aux == nullptr) {
        cudaStreamCreateWithFlags(&s_aux, cudaStreamNonBlocking);
        cudaEventCreateWithFlags(&ev_fork, cudaEventDisableTiming);
        cudaEventCreateWithFlags(&ev_scan, cudaEventDisableTiming);
        cudaFuncSetAttribute((const void*)mem_mlp_kernel,
                             cudaFuncAttributeMaxDynamicSharedMemorySize, smem_mem);
        cudaFuncSetAttribute((const void*)final_kernel,
                             cudaFuncAttributeMaxDynamicSharedMemorySize, smem_final);
    }

    void* p_s;
    cudaGetSymbolAddress(&p_s, g_s);

    // Main stream: counters + weight transpose
    zero_kernel<<<(E_TOT + 255) / 256, 256>>>();
    cudaEventRecord(ev_fork, 0);

    // Aux stream: mask scan (independent of MLP), overlapped
    cudaStreamWaitEvent(s_aux, ev_fork, 0);
    scan_lists_kernel<<<dim3(N_NODES, 8), 128, 0, s_aux>>>(mask);
    cudaEventRecord(ev_scan, s_aux);

    // Main stream: memory MLP (concurrent with scan)
    wtrans_kernel<<<(69632 + 255) / 256, 256>>>(W1m, W2m, W1a, W2a);
    mem_mlp_kernel<<<E_TOT / 64, 256, smem_mem>>>(state, b1m, (float*)p_s);

    // Join: node gather needs g_s + node lists
    cudaStreamWaitEvent(0, ev_scan, 0);
    node_sum_kernel<<<N_NODES, 128>>>();
    final_kernel<<<E_TOT / 64, 256, smem_final>>>(feature, b1a, out);
}

// round 9
// speedup vs baseline: 1.5813x; 1.1996x over previous
#include <cuda_runtime.h>
#include <cstdint>

#define E_TOT   32768
#define N_NODES 2048
#define D       128
#define DF      32
#define DCAT    160
#define MAXED   64     // nodes per edge cap (mean ~10.2)
#define MAXNE   256    // edges per node cap (mean ~164)
#define XS      132    // x-tile stride: 16B-aligned rows for float4 LDS

// Scratch (__device__ globals: allocation-free rule)
__device__ float g_s [(size_t)E_TOT * D];
__device__ float g_node[(size_t)N_NODES * D];
__device__ int   g_edeg[E_TOT];
__device__ int   g_enode[(size_t)E_TOT * MAXED];
__device__ int   g_ncnt[N_NODES];
__device__ int   g_nlist[(size_t)N_NODES * MAXNE];
// Pre-transposed weights (k-major)
__device__ float g_w1mT[D * D];
__device__ float g_w2mT[D * D];
__device__ float g_w1aT[DCAT * D];
__device__ float g_w2aT[D * D];

__device__ __forceinline__ float lsig(float x) {
    return fminf(x, 0.0f) - log1pf(__expf(-fabsf(x)));
}

// Packed dual-FMA (sm_103a FFMA2)
__device__ __forceinline__ void ffma2(float2& d, const float2 a, const float2 b) {
    asm("fma.rn.f32x2 %0, %1, %2, %0;"
        : "+l"(*reinterpret_cast<unsigned long long*>(&d))
        : "l"(*reinterpret_cast<const unsigned long long*>(&a)),
          "l"(*reinterpret_cast<const unsigned long long*>(&b)));
}

__global__ void zero_kernel() {
    int i = blockIdx.x * blockDim.x + threadIdx.x;
    if (i < E_TOT) g_edeg[i] = 0;
    if (i < N_NODES) g_ncnt[i] = 0;
}

__global__ void wtrans_kernel(const float* __restrict__ W1m, const float* __restrict__ W2m,
                              const float* __restrict__ W1a, const float* __restrict__ W2a) {
    int i = blockIdx.x * blockDim.x + threadIdx.x;
    if (i < 16384) {
        int r = i >> 7, c = i & 127;
        g_w1mT[c * 128 + r] = W1m[i];
    } else if (i < 32768) {
        int j = i - 16384; int r = j >> 7, c = j & 127;
        g_w2mT[c * 128 + r] = W2m[j];
    } else if (i < 53248) {
        int j = i - 32768; int r = j / 160, c = j - r * 160;
        g_w1aT[c * 128 + r] = W1a[j];
    } else if (i < 69632) {
        int j = i - 53248; int r = j >> 7, c = j & 127;
        g_w2aT[c * 128 + r] = W2a[j];
    }
}

// ---------------------------------------------------------------------------
// 8x8 micro-tile GEMM step: 32B of weights feed 64 MACs (0.5 B/MAC).
// acc: float2[8][4].  XK must be 16B-aligned (XS=132 guarantees it).
// ---------------------------------------------------------------------------
#define GEMM_K_STEP8(XK, WK, ACC)                                              \
    {                                                                          \
        const float4* _wkp = (WK);                                             \
        float4 _w0 = __ldg(_wkp), _w1 = __ldg(_wkp + 1);                       \
        const float4* _xp = reinterpret_cast<const float4*>(XK);               \
        float4 _xa = _xp[0], _xb = _xp[1];                                     \
        float2 _p0 = make_float2(_w0.x, _w0.y);                                \
        float2 _p1 = make_float2(_w0.z, _w0.w);                                \
        float2 _p2 = make_float2(_w1.x, _w1.y);                                \
        float2 _p3 = make_float2(_w1.z, _w1.w);                                \
        float _av[8] = {_xa.x, _xa.y, _xa.z, _xa.w, _xb.x, _xb.y, _xb.z, _xb.w};\
        _Pragma("unroll")                                                      \
        for (int _i = 0; _i < 8; ++_i) {                                       \
            float2 _ab = make_float2(_av[_i], _av[_i]);                        \
            ffma2(ACC[_i][0], _ab, _p0); ffma2(ACC[_i][1], _ab, _p1);          \
            ffma2(ACC[_i][2], _ab, _p2); ffma2(ACC[_i][3], _ab, _p3);          \
        }                                                                      \
    }

#define ACC_CLEAR8(ACC)                                                        \
    _Pragma("unroll") for (int i = 0; i < 8; ++i)                              \
    _Pragma("unroll") for (int j = 0; j < 4; ++j) ACC[i][j] = make_float2(0.f, 0.f);

// ---------------------------------------------------------------------------
// Fused memory MLP: g_s = ls( ls(state @ W1m^T + b1m) @ W2m^T )
// 128 rows/block, 256 threads, 8x8 micro-tile.
// ---------------------------------------------------------------------------
__global__ void __launch_bounds__(256, 2) mem_mlp_kernel(const float* __restrict__ state,
                                                         const float* __restrict__ b1m,
                                                         float* __restrict__ sout) {
    extern __shared__ float sm[];
    float* xT = sm;              // [128][XS]
    float* sb = xT + 128 * XS;   // [128]

    const int tid = threadIdx.x;
    const int e0  = blockIdx.x * 128;

    const float* inb = state + (size_t)e0 * 128;
    for (int idx = tid; idx < 128 * 128; idx += 256) {
        int m = idx >> 7, k = idx & 127;
        xT[k * XS + m] = inb[idx];
    }
    if (tid < 128) sb[tid] = b1m[tid];
    __syncthreads();

    const int tr = tid >> 4, tc = tid & 15;   // tr: 0..15 (8 rows each), tc: 0..15 (8 cols)
    float2 acc[8][4];
    ACC_CLEAR8(acc)

    const float4* wp1_ = reinterpret_cast<const float4*>(g_w1mT) + tc * 2;
#pragma unroll 4
    for (int k = 0; k < 128; ++k)
        GEMM_K_STEP8(xT + k * XS + tr * 8, wp1_ + k * 32, acc)

    // bias + lsig in-place, then restage transposed
#pragma unroll
    for (int i = 0; i < 8; ++i)
#pragma unroll
        for (int j = 0; j < 4; ++j) {
            int col = tc * 8 + j * 2;
            acc[i][j].x = lsig(acc[i][j].x + sb[col]);
            acc[i][j].y = lsig(acc[i][j].y + sb[col + 1]);
        }
    __syncthreads();
#pragma unroll
    for (int i = 0; i < 8; ++i)
#pragma unroll
        for (int j = 0; j < 4; ++j) {
            xT[(tc * 8 + j * 2)     * XS + tr * 8 + i] = acc[i][j].x;
            xT[(tc * 8 + j * 2 + 1) * XS + tr * 8 + i] = acc[i][j].y;
        }
    __syncthreads();

    ACC_CLEAR8(acc)
    const float4* wp2_ = reinterpret_cast<const float4*>(g_w2mT) + tc * 2;
#pragma unroll 4
    for (int k = 0; k < 128; ++k)
        GEMM_K_STEP8(xT + k * XS + tr * 8, wp2_ + k * 32, acc)

#pragma unroll
    for (int i = 0; i < 8; ++i) {
        int row = e0 + tr * 8 + i;
        float r[8];
#pragma unroll
        for (int j = 0; j < 4; ++j) {
            r[j * 2]     = lsig(acc[i][j].x);
            r[j * 2 + 1] = lsig(acc[i][j].y);
        }
        float4* op = reinterpret_cast<float4*>(sout + (size_t)row * 128 + tc * 8);
        op[0] = make_float4(r[0], r[1], r[2], r[3]);
        op[1] = make_float4(r[4], r[5], r[6], r[7]);
    }
}

// ---------------------------------------------------------------------------
// Pure mask scan (overlapped with mem_mlp): builds both adjacency lists.
// ---------------------------------------------------------------------------
__global__ void __launch_bounds__(128) scan_lists_kernel(const float* __restrict__ mask) {
    const int n = blockIdx.x;
    const int slice = blockIdx.y;
    const int t = threadIdx.x;

    const float4* mrow = reinterpret_cast<const float4*>(mask + (size_t)n * E_TOT)
                         + slice * 1024;
    float4 mv[8];
#pragma unroll
    for (int q = 0; q < 8; ++q) mv[q] = __ldcs(&mrow[q * 128 + t]);

#pragma unroll
    for (int q = 0; q < 8; ++q) {
        int e0 = slice * 4096 + q * 512 + t * 4;
        float vals[4] = {mv[q].x, mv[q].y, mv[q].z, mv[q].w};
#pragma unroll
        for (int u = 0; u < 4; ++u) {
            if (vals[u] != 0.0f) {
                int e = e0 + u;
                int p = atomicAdd(&g_ncnt[n], 1);
                if (p < MAXNE) g_nlist[(size_t)n * MAXNE + p] = e;
                int q2 = atomicAdd(&g_edeg[e], 1);
                if (q2 < MAXED) g_enode[(size_t)e * MAXED + q2] = n;
            }
        }
    }
}

// ---------------------------------------------------------------------------
// Node gather: g_node[n][:] = sum of g_s rows (L2-bound).
// ---------------------------------------------------------------------------
__global__ void __launch_bounds__(128) node_sum_kernel() {
    const int n = blockIdx.x;
    const int t = threadIdx.x;
    int c = g_ncnt[n];
    if (c > MAXNE) c = MAXNE;
    const int* lst = g_nlist + (size_t)n * MAXNE;

    float a0 = 0.f, a1 = 0.f, a2 = 0.f, a3 = 0.f;
    int i = 0;
    for (; i + 4 <= c; i += 4) {
        int e0 = __ldg(lst + i), e1 = __ldg(lst + i + 1);
        int e2 = __ldg(lst + i + 2), e3 = __ldg(lst + i + 3);
        a0 += g_s[(size_t)e0 * 128 + t];
        a1 += g_s[(size_t)e1 * 128 + t];
        a2 += g_s[(size_t)e2 * 128 + t];
        a3 += g_s[(size_t)e3 * 128 + t];
    }
    for (; i < c; ++i) a0 += g_s[(size_t)__ldg(lst + i) * 128 + t];
    g_node[(size_t)n * 128 + t] = (a0 + a1) + (a2 + a3);
}

// ---------------------------------------------------------------------------
// Fused final stage: 128 rows/block, 256 threads, 8x8 micro-tile.
// agg build: 2 threads/edge, two sequential 32-dim passes.
// ---------------------------------------------------------------------------
__global__ void __launch_bounds__(256, 2) final_kernel(const float* __restrict__ feature,
                                                       const float* __restrict__ b1a,
                                                       float* __restrict__ out) {
    extern __shared__ float sm[];
    float* xT = sm;                   // [160][XS]; rows 0..127 recycled for hidden
    float* sb = xT + DCAT * XS;       // [128]

    const int tid = threadIdx.x;
    const int e0  = blockIdx.x * 128;

    // agg: 2 threads per edge; each covers 64 dims in two 32-dim passes
    {
        int m   = tid >> 1;
        int kb0 = (tid & 1) << 6;
        int e   = e0 + m;
        int d = g_edeg[e];
        if (d > MAXED) d = MAXED;
        const int* nl = g_enode + (size_t)e * MAXED;
#pragma unroll
        for (int half = 0; half < 2; ++half) {
            int kb = kb0 + half * 32;
            float v[32];
            const float4* sp = reinterpret_cast<const float4*>(g_s + (size_t)e * 128 + kb);
#pragma unroll
            for (int q = 0; q < 8; ++q) {
                float4 f = sp[q];
                v[q * 4 + 0] = -f.x; v[q * 4 + 1] = -f.y;
                v[q * 4 + 2] = -f.z; v[q * 4 + 3] = -f.w;
            }
            for (int i = 0; i < d; ++i) {
                int nn = __ldg(nl + i);
                const float4* np = reinterpret_cast<const float4*>(g_node + (size_t)nn * 128 + kb);
#pragma unroll
                for (int q = 0; q < 8; ++q) {
                    float4 f = np[q];
                    v[q * 4 + 0] += f.x; v[q * 4 + 1] += f.y;
                    v[q * 4 + 2] += f.z; v[q * 4 + 3] += f.w;
                }
            }
#pragma unroll
            for (int kk = 0; kk < 32; ++kk) xT[(kb + kk) * XS + m] = v[kk];
        }
    }
    for (int idx = tid; idx < 128 * DF; idx += 256) {
        int m = idx >> 5, k = idx & 31;
        xT[(128 + k) * XS + m] = feature[(size_t)(e0 + m) * DF + k];
    }
    if (tid < 128) sb[tid] = b1a[tid];
    __syncthreads();

    const int tr = tid >> 4, tc = tid & 15;
    float2 acc[8][4];
    ACC_CLEAR8(acc)

    const float4* wp1_ = reinterpret_cast<const float4*>(g_w1aT) + tc * 2;
#pragma unroll 4
    for (int k = 0; k < DCAT; ++k)
        GEMM_K_STEP8(xT + k * XS + tr * 8, wp1_ + k * 32, acc)

#pragma unroll
    for (int i = 0; i < 8; ++i)
#pragma unroll
        for (int j = 0; j < 4; ++j) {
            int col = tc * 8 + j * 2;
            acc[i][j].x = lsig(acc[i][j].x + sb[col]);
            acc[i][j].y = lsig(acc[i][j].y + sb[col + 1]);
        }
    __syncthreads();
#pragma unroll
    for (int i = 0; i < 8; ++i)
#pragma unroll
        for (int j = 0; j < 4; ++j) {
            xT[(tc * 8 + j * 2)     * XS + tr * 8 + i] = acc[i][j].x;
            xT[(tc * 8 + j * 2 + 1) * XS + tr * 8 + i] = acc[i][j].y;
        }
    __syncthreads();

    ACC_CLEAR8(acc)
    const float4* wp2_ = reinterpret_cast<const float4*>(g_w2aT) + tc * 2;
#pragma unroll 4
    for (int k = 0; k < 128; ++k)
        GEMM_K_STEP8(xT + k * XS + tr * 8, wp2_ + k * 32, acc)

#pragma unroll
    for (int i = 0; i < 8; ++i) {
        int row = e0 + tr * 8 + i;
        float r[8];
#pragma unroll
        for (int j = 0; j < 4; ++j) {
            r[j * 2]     = lsig(acc[i][j].x);
            r[j * 2 + 1] = lsig(acc[i][j].y);
        }
        float4* op = reinterpret_cast<float4*>(out + (size_t)row * 128 + tc * 8);
        op[0] = make_float4(r[0], r[1], r[2], r[3]);
        op[1] = make_float4(r[4], r[5], r[6], r[7]);
    }
}

// ---------------------------------------------------------------------------
extern "C" void kernel_launch(void* const* d_in, const int* in_sizes, int n_in,
                              void* d_out, int out_size) {
    const float* state   = (const float*)d_in[0];
    const float* feature = (const float*)d_in[1];
    const float* mask    = (const float*)d_in[2];
    const float* W1m = (const float*)d_in[4];
    const float* b1m = (const float*)d_in[5];
    const float* W2m = (const float*)d_in[6];
    const float* W1a = (const float*)d_in[7];
    const float* b1a = (const float*)d_in[8];
    const float* W2a = (const float*)d_in[9];
    float* out = (float*)d_out;

    const int smem_mem   = (128 * XS + 128) * 4;   // ~68 KB
    const int smem_final = (DCAT * XS + 128) * 4;  // ~85 KB

    static cudaStream_t s_aux = nullptr;
    static cudaEvent_t ev_fork = nullptr, ev_scan = nullptr;
    if (s_aux == nullptr) {
        cudaStreamCreateWithFlags(&s_aux, cudaStreamNonBlocking);
        cudaEventCreateWithFlags(&ev_fork, cudaEventDisableTiming);
        cudaEventCreateWithFlags(&ev_scan, cudaEventDisableTiming);
        cudaFuncSetAttribute((const void*)mem_mlp_kernel,
                             cudaFuncAttributeMaxDynamicSharedMemorySize, smem_mem);
        cudaFuncSetAttribute((const void*)final_kernel,
                             cudaFuncAttributeMaxDynamicSharedMemorySize, smem_final);
    }

    void* p_s;
    cudaGetSymbolAddress(&p_s, g_s);

    zero_kernel<<<(E_TOT + 255) / 256, 256>>>();
    cudaEventRecord(ev_fork, 0);

    cudaStreamWaitEvent(s_aux, ev_fork, 0);
    scan_lists_kernel<<<dim3(N_NODES, 8), 128, 0, s_aux>>>(mask);
    cudaEventRecord(ev_scan, s_aux);

    wtrans_kernel<<<(69632 + 255) / 256, 256>>>(W1m, W2m, W1a, W2a);
    mem_mlp_kernel<<<E_TOT / 128, 256, smem_mem>>>(state, b1m, (float*)p_s);

    cudaStreamWaitEvent(0, ev_scan, 0);
    node_sum_kernel<<<N_NODES, 128>>>();
    final_kernel<<<E_TOT / 128, 256, smem_final>>>(feature, b1a, out);
}